// round 11
// baseline (speedup 1.0000x reference)
#include <cuda_runtime.h>
#include <cstdint>

#define DHN 512
#define BN  64
#define TN  1024
#define NRANK 4          // CTAs per cluster
#define DSL 128          // d/h slice per rank
#define NB  2            // batches per cluster

__device__ float g_sig[(size_t)BN*DHN*TN];   // sigma(x_new) for rnn_out
__device__ float g_part[8][BN][TN];

__device__ __forceinline__ float sigmoidf_(float x){ return 1.0f/(1.0f + __expf(-x)); }

__device__ __forceinline__ unsigned long long pack2(float lo, float hi){
    unsigned long long r; asm("mov.b64 %0, {%1,%2};" : "=l"(r) : "f"(lo), "f"(hi)); return r;
}
__device__ __forceinline__ void unpack2(unsigned long long v, float &lo, float &hi){
    asm("mov.b64 {%0,%1}, %2;" : "=f"(lo), "=f"(hi) : "l"(v));
}
__device__ __forceinline__ void fma2(unsigned long long &acc, unsigned long long a, unsigned long long b){
    asm("fma.rn.f32x2 %0, %1, %2, %3;" : "=l"(acc) : "l"(a), "l"(b), "l"(acc));
}
// bf16x2 word -> packed f32x2: fp32(bf16) is just bf16<<16
__device__ __forceinline__ unsigned long long bf2f2(uint32_t v){
    uint32_t lo, hi; unsigned long long r;
    asm("shl.b32 %0, %1, 16;"          : "=r"(lo) : "r"(v));
    asm("and.b32 %0, %1, 0xffff0000;"  : "=r"(hi) : "r"(v));
    asm("mov.b64 %0, {%1,%2};" : "=l"(r) : "r"(lo), "r"(hi));
    return r;
}
__device__ __forceinline__ uint32_t f2bf2(float lo, float hi){
    uint32_t r;
    asm("cvt.rn.bf16x2.f32 %0, %1, %2;" : "=r"(r) : "f"(hi), "f"(lo)); // first src -> high half
    return r;
}
__device__ __forceinline__ uint32_t smem_u32(const void* p){
    uint32_t a; asm("{ .reg .u64 t; cvta.to.shared.u64 t, %1; cvt.u32.u64 %0, t; }" : "=r"(a) : "l"(p)); return a;
}
__device__ __forceinline__ uint32_t mapa_(uint32_t addr, uint32_t rank){
    uint32_t r; asm("mapa.shared::cluster.u32 %0, %1, %2;" : "=r"(r) : "r"(addr), "r"(rank)); return r;
}
__device__ __forceinline__ void st_cluster_b64(uint32_t addr, unsigned long long v){
    asm volatile("st.shared::cluster.b64 [%0], %1;" :: "r"(addr), "l"(v) : "memory");
}
__device__ __forceinline__ void cluster_arrive_(){
    asm volatile("barrier.cluster.arrive.aligned;" ::: "memory");
}
__device__ __forceinline__ void cluster_wait_(){
    asm volatile("barrier.cluster.wait.aligned;" ::: "memory");
}
__device__ __forceinline__ uint32_t ctarank_(){
    uint32_t r; asm("mov.u32 %0, %%cluster_ctarank;" : "=r"(r)); return r;
}

// 32 clusters x 4 CTAs x 512 threads.
// Cluster c: batches {2c, 2c+1}. Rank k: d-slice AND h-slice [128k, 128k+128).
// Thread tid = global h row: full 128-d partial dot in-thread, both batches.
//   d 0..63  : fp32 in 32 f32x2 registers
//   d 64..127: bf16x2 in 32 u32 registers (expanded on the fly: SHL/AND)
// Zero W memory traffic in the loop. Partials shipped packed (8B) to the
// h-owning rank; r never leaves the producing CTA.
__global__ void __cluster_dims__(NRANK,1,1) __launch_bounds__(512,1)
rnn_main(const float* __restrict__ u, const float* __restrict__ r0,
         const float* __restrict__ noise, const float* __restrict__ win,
         const float* __restrict__ w_raw, const float* __restrict__ taus,
         float* __restrict__ xs)
{
    __shared__ __align__(16) float u_sh[NB*TN];            // 8 KB
    __shared__ __align__(16) float r_own[2][NB][DSL];      // 2 KB
    __shared__ __align__(16) float p_sh[2][NRANK][DSL][NB];// 8 KB  [buf][src][h][b]
    __shared__ __align__(16) float stg_x[16][NB][DSL];     // 16 KB
    __shared__ __align__(16) float stg_s[16][NB][DSL];     // 16 KB

    const int tid   = threadIdx.x;            // == global h row
    const uint32_t rank = ctarank_();
    const int cid   = blockIdx.x / NRANK;
    const int bbase = cid * NB;

    // u slices for this cluster's 2 batches
    for (int i = tid; i < NB*TN; i += 512)
        u_sh[i] = u[(size_t)bbase*TN + i];

    // ---- W row: |_w| (m is diag(+-1)); d 0..63 fp32 regs, d 64..127 bf16 regs ----
    unsigned long long w2[32];
    uint32_t wb[32];
    {
        const float* wr = w_raw + (size_t)tid*DHN + (int)rank*DSL;
        #pragma unroll
        for (int k = 0; k < 32; k++)
            w2[k] = pack2(fabsf(wr[2*k]), fabsf(wr[2*k+1]));
        #pragma unroll
        for (int j = 0; j < 32; j++)
            wb[j] = f2bf2(fabsf(wr[64 + 2*j]), fabsf(wr[64 + 2*j + 1]));
    }

    // epilogue thread (tid<256): b = tid>>7, hl = tid&127, hg = rank*128+hl
    const int eb  = tid >> 7;
    const int ehl = tid & 127;
    const int ehg = (int)rank*DSL + ehl;
    const int ebg = bbase + eb;
    float a_h = 0.f, win_h = 0.f, s = 0.f;
    if (tid < 256){
        a_h   = 1.0f/taus[ehg];
        win_h = win[ehg];
        s     = r0[(size_t)ebg*DHN + ehg];
        r_own[0][eb][ehl] = sigmoidf_(s);    // buf 0
    }

    // delivery target: packed (b0,b1) partial for h=tid goes to rank dj = tid>>7
    const uint32_t dj  = (uint32_t)(tid >> 7);
    const int      dhl = tid & 127;
    const uint32_t pdst0 = mapa_(smem_u32(&p_sh[0][(int)rank][dhl][0]), dj);
    const uint32_t PBUF_STRIDE = (uint32_t)(NRANK*DSL*NB*4);   // buf stride in bytes

    __syncthreads();   // r_own[0], u_sh ready

    const float* np = noise + (size_t)ebg*DHN + ehg;   // + t*BN*DHN per step

    for (int t = 0; t < TN; t++){
        const int buf = t & 1;

        // prefetch noise for epilogue (used after the barrier)
        float nv = 0.f;
        if (tid < 256) nv = np[(size_t)t*BN*DHN];

        // ---- matvec: full 128-d dot for h=tid, both batches ----
        unsigned long long a00=0ull, a01=0ull, a10=0ull, a11=0ull;
        const ulonglong2* rp0 = (const ulonglong2*)&r_own[buf][0][0];
        const ulonglong2* rp1 = (const ulonglong2*)&r_own[buf][1][0];
        #pragma unroll
        for (int k = 0; k < 16; k++){
            ulonglong2 v0 = rp0[k], v1 = rp1[k];
            fma2(a00, w2[2*k],   v0.x); fma2(a01, w2[2*k+1], v0.y);
            fma2(a10, w2[2*k],   v1.x); fma2(a11, w2[2*k+1], v1.y);
        }
        #pragma unroll
        for (int k = 0; k < 8; k++){
            unsigned long long w0 = bf2f2(wb[4*k+0]);
            unsigned long long w1 = bf2f2(wb[4*k+1]);
            unsigned long long wX = bf2f2(wb[4*k+2]);
            unsigned long long w3 = bf2f2(wb[4*k+3]);
            ulonglong2 v0a = rp0[16+2*k], v0b = rp0[17+2*k];
            ulonglong2 v1a = rp1[16+2*k], v1b = rp1[17+2*k];
            fma2(a00, w0, v0a.x); fma2(a01, w1, v0a.y);
            fma2(a00, wX, v0b.x); fma2(a01, w3, v0b.y);
            fma2(a10, w0, v1a.x); fma2(a11, w1, v1a.y);
            fma2(a10, wX, v1b.x); fma2(a11, w3, v1b.y);
        }
        float pb0, pb1;
        { float l0,h0,l1,h1; unpack2(a00,l0,h0); unpack2(a01,l1,h1); pb0 = (l0+h0)+(l1+h1); }
        { float l0,h0,l1,h1; unpack2(a10,l0,h0); unpack2(a11,l1,h1); pb1 = (l0+h0)+(l1+h1); }

        // ---- ship packed partials to the h-owning rank (3/4 remote, 1/4 self) ----
        st_cluster_b64(pdst0 + (buf ? PBUF_STRIDE : 0u), pack2(pb0, pb1));

        cluster_arrive_();

        // ---- coalesced flush of the PREVIOUS 16-step block, hidden in the
        //      arrive->wait gap (stg slots stable: epilogue writes only after wait) ----
        if ((t & 15) == 0 && t){
            const int t0 = t - 16;
            #pragma unroll
            for (int it = 0; it < 2; it++){
                int idx = tid + it*512;            // 1024 quads
                int q  = idx & 3;
                int hl = (idx >> 2) & 127;
                int b  = idx >> 9;
                float4 vx, vs;
                vx.x = stg_x[4*q+0][b][hl];
                vx.y = stg_x[4*q+1][b][hl];
                vx.z = stg_x[4*q+2][b][hl];
                vx.w = stg_x[4*q+3][b][hl];
                vs.x = stg_s[4*q+0][b][hl];
                vs.y = stg_s[4*q+1][b][hl];
                vs.z = stg_s[4*q+2][b][hl];
                vs.w = stg_s[4*q+3][b][hl];
                size_t row = ((size_t)(bbase+b)*DHN + (int)rank*DSL + hl)*TN + t0 + 4*q;
                *(float4*)(xs    + row) = vx;
                *(float4*)(g_sig + row) = vs;
            }
        }

        cluster_wait_();   // partials visible cluster-wide

        // ---- reduce + epilogue for own h-slice ----
        if (tid < 256){
            const float* pb = &p_sh[buf][0][ehl][eb];
            float dot = (pb[0] + pb[DSL*NB]) + (pb[2*DSL*NB] + pb[3*DSL*NB]);
            float xn = (1.0f - a_h)*s + a_h*dot + win_h*u_sh[eb*TN + t] + 0.1f*nv;
            stg_x[t&15][eb][ehl] = xn;
            s = sigmoidf_(xn);
            stg_s[t&15][eb][ehl] = s;
            r_own[(t+1)&1][eb][ehl] = sigmoidf_(s);   // next r, local only
        }
        __syncthreads();
    }

    // final block flush (t = 1008..1023)
    {
        const int t0 = TN - 16;
        #pragma unroll
        for (int it = 0; it < 2; it++){
            int idx = tid + it*512;
            int q  = idx & 3;
            int hl = (idx >> 2) & 127;
            int b  = idx >> 9;
            float4 vx, vs;
            vx.x = stg_x[4*q+0][b][hl];
            vx.y = stg_x[4*q+1][b][hl];
            vx.z = stg_x[4*q+2][b][hl];
            vx.w = stg_x[4*q+3][b][hl];
            vs.x = stg_s[4*q+0][b][hl];
            vs.y = stg_s[4*q+1][b][hl];
            vs.z = stg_s[4*q+2][b][hl];
            vs.w = stg_s[4*q+3][b][hl];
            size_t row = ((size_t)(bbase+b)*DHN + (int)rank*DSL + hl)*TN + t0 + 4*q;
            *(float4*)(xs    + row) = vx;
            *(float4*)(g_sig + row) = vs;
        }
    }

    cluster_arrive_();   // exit safety: no CTA leaves while peers' remote
    cluster_wait_();     // stores could still be in flight
}

// Partial dot products over 64-h chunks: pure DRAM streaming, zero MUFU.
__global__ void __launch_bounds__(256)
rnn_out_part(const float* __restrict__ wout)
{
    const int b  = blockIdx.x >> 3;
    const int hc = blockIdx.x & 7;
    __shared__ float wsh[64];
    if (threadIdx.x < 64) wsh[threadIdx.x] = wout[hc*64 + threadIdx.x];
    __syncthreads();

    const float4* base = (const float4*)(g_sig + ((size_t)b*DHN + hc*64)*TN);
    float a0=0.f, a1=0.f, a2=0.f, a3=0.f;
    #pragma unroll 4
    for (int h = 0; h < 64; h++){
        float wv = wsh[h];
        float4 v = base[(size_t)h*(TN/4) + threadIdx.x];
        a0 = fmaf(wv, v.x, a0);
        a1 = fmaf(wv, v.y, a1);
        a2 = fmaf(wv, v.z, a2);
        a3 = fmaf(wv, v.w, a3);
    }
    float4 o; o.x=a0; o.y=a1; o.z=a2; o.w=a3;
    ((float4*)g_part[hc][b])[threadIdx.x] = o;
}

__global__ void __launch_bounds__(256)
rnn_combine(const float* __restrict__ bias, float* __restrict__ out)
{
    const int b = blockIdx.x;
    float4 acc = {0.f,0.f,0.f,0.f};
    #pragma unroll
    for (int c = 0; c < 8; c++){
        float4 p = ((const float4*)g_part[c][b])[threadIdx.x];
        acc.x += p.x; acc.y += p.y; acc.z += p.z; acc.w += p.w;
    }
    float bz = bias[0];
    acc.x += bz; acc.y += bz; acc.z += bz; acc.w += bz;
    ((float4*)(out + (size_t)b*TN))[threadIdx.x] = acc;
}

extern "C" void kernel_launch(void* const* d_in, const int* in_sizes, int n_in,
                              void* d_out, int out_size)
{
    // metadata order: u, r0, noise, win, m, wout, _w, taus, bias
    const float* u     = (const float*)d_in[0];
    const float* r0    = (const float*)d_in[1];
    const float* noise = (const float*)d_in[2];
    const float* win   = (const float*)d_in[3];
    const float* wout  = (const float*)d_in[5];
    const float* w_raw = (const float*)d_in[6];
    const float* taus  = (const float*)d_in[7];
    const float* bias  = (const float*)d_in[8];

    float* out = (float*)d_out;                 // outputs (B, T, 1)
    float* xs  = out + (size_t)BN * TN;         // xs (B, DH, T)

    rnn_main<<<32*NRANK, 512>>>(u, r0, noise, win, w_raw, taus, xs);
    rnn_out_part<<<BN*8, 256>>>(wout);
    rnn_combine<<<BN, 256>>>(bias, out);
}

// round 12
// speedup vs baseline: 2.2459x; 2.2459x over previous
#include <cuda_runtime.h>
#include <cstdint>

#define DHN 512
#define BN  64
#define TN  1024
#define NRANK 4          // CTAs per cluster
#define DSL 128          // d/h slice per rank
#define NB  2            // batches per cluster

// dynamic smem layout (4-byte units)
#define OFF_WB 0                     // [512][36] u32 bf16x2 W rows (73728 B)
#define OFF_U  18432                 // [NB][TN]
#define OFF_R  (OFF_U + NB*TN)       // [2][NB][144] swizzled r
#define OFF_P  (OFF_R + 2*NB*144)    // [2][NRANK][DSL][2] partials
#define OFF_SX (OFF_P + 2*NRANK*DSL*2)
#define OFF_SS (OFF_SX + 16*NB*DSL)
#define SMEM_FLOATS (OFF_SS + 16*NB*DSL)
#define SMEM_BYTES (SMEM_FLOATS*4)

__device__ float g_sig[(size_t)BN*DHN*TN];   // sigma(x_new) for rnn_out
__device__ float g_part[8][BN][TN];

__device__ __forceinline__ float sigmoidf_(float x){ return 1.0f/(1.0f + __expf(-x)); }

__device__ __forceinline__ unsigned long long pack2(float lo, float hi){
    unsigned long long r; asm("mov.b64 %0, {%1,%2};" : "=l"(r) : "f"(lo), "f"(hi)); return r;
}
__device__ __forceinline__ void unpack2(unsigned long long v, float &lo, float &hi){
    asm("mov.b64 {%0,%1}, %2;" : "=f"(lo), "=f"(hi) : "l"(v));
}
__device__ __forceinline__ void fma2(unsigned long long &acc, unsigned long long a, unsigned long long b){
    asm("fma.rn.f32x2 %0, %1, %2, %3;" : "=l"(acc) : "l"(a), "l"(b), "l"(acc));
}
// bf16x2 word -> packed f32x2 (fp32(bf16) == bf16<<16)
__device__ __forceinline__ unsigned long long bf2f2(uint32_t v){
    uint32_t lo, hi; unsigned long long r;
    asm("shl.b32 %0, %1, 16;"          : "=r"(lo) : "r"(v));
    asm("and.b32 %0, %1, 0xffff0000;"  : "=r"(hi) : "r"(v));
    asm("mov.b64 %0, {%1,%2};" : "=l"(r) : "r"(lo), "r"(hi));
    return r;
}
__device__ __forceinline__ uint32_t f2bf2(float lo, float hi){
    uint32_t r;
    asm("cvt.rn.bf16x2.f32 %0, %1, %2;" : "=r"(r) : "f"(hi), "f"(lo));
    return r;
}
__device__ __forceinline__ uint32_t smem_u32(const void* p){
    uint32_t a; asm("{ .reg .u64 t; cvta.to.shared.u64 t, %1; cvt.u32.u64 %0, t; }" : "=r"(a) : "l"(p)); return a;
}
__device__ __forceinline__ uint32_t mapa_(uint32_t addr, uint32_t rank){
    uint32_t r; asm("mapa.shared::cluster.u32 %0, %1, %2;" : "=r"(r) : "r"(addr), "r"(rank)); return r;
}
__device__ __forceinline__ void st_cluster_b64(uint32_t addr, unsigned long long v){
    asm volatile("st.shared::cluster.b64 [%0], %1;" :: "r"(addr), "l"(v) : "memory");
}
__device__ __forceinline__ void cluster_arrive_(){
    asm volatile("barrier.cluster.arrive.aligned;" ::: "memory");
}
__device__ __forceinline__ void cluster_wait_(){
    asm volatile("barrier.cluster.wait.aligned;" ::: "memory");
}
__device__ __forceinline__ uint32_t ctarank_(){
    uint32_t r; asm("mov.u32 %0, %%cluster_ctarank;" : "=r"(r)); return r;
}
// swizzled r index: pad 4 floats per 32-float d-group (conflict-free dg reads)
__device__ __forceinline__ int swz(int d){ return d + ((d >> 5) << 2); }

// 32 clusters x 4 CTAs x 512 threads.
// Cluster c: batches {2c,2c+1}. Rank k: d-slice AND h-slice [128k,128k+128).
// Thread: dg = tid&3 -> d-chunk [rank*128+dg*32, +32); h-rows (tid&~3)..+3.
//   d j 0..15 : fp32, 32 f32x2 register pairs (4h x 8 pairs)
//   d j 16..31: bf16x2, 32-word smem row (read once/step, both batches)
// dg-partials reduce-scattered via shfl (lane dg ends with h-row = tid), then
// one packed b64 DSMEM ship to the h-owning rank.
__global__ void __cluster_dims__(NRANK,1,1) __launch_bounds__(512,1)
rnn_main(const float* __restrict__ u, const float* __restrict__ r0,
         const float* __restrict__ noise, const float* __restrict__ win,
         const float* __restrict__ w_raw, const float* __restrict__ taus,
         float* __restrict__ xs)
{
    extern __shared__ __align__(16) float sm[];
    uint32_t* W_bh = (uint32_t*)(sm + OFF_WB);   // [512][36]
    float* u_sh  = sm + OFF_U;                   // [NB][TN]
    float* r_own = sm + OFF_R;                   // [2][NB][144]
    float* p_sh  = sm + OFF_P;                   // [2][NRANK][DSL][2]
    float* stg_x = sm + OFF_SX;                  // [16][NB][DSL]
    float* stg_s = sm + OFF_SS;                  // [16][NB][DSL]

    const int tid = threadIdx.x;
    const int dg  = tid & 3;
    const int hb  = tid & ~3;                    // first of 4 h-rows
    const uint32_t rank = ctarank_();
    const int cid   = blockIdx.x / NRANK;
    const int bbase = cid * NB;
    const int d0    = (int)rank*DSL + dg*32;

    for (int i = tid; i < NB*TN; i += 512)
        u_sh[i] = u[(size_t)bbase*TN + i];

    // ---- W = |_w| (m is diag(+-1)) ----
    unsigned long long w2[32];                   // [i 4][p 8] fp32 pairs, j 0..15
    {
        #pragma unroll
        for (int i = 0; i < 4; i++){
            const float* wr = w_raw + (size_t)(hb + i)*DHN + d0;
            #pragma unroll
            for (int p = 0; p < 8; p++)
                w2[i*8 + p] = pack2(fabsf(wr[2*p]), fabsf(wr[2*p+1]));
        }
        uint32_t* wrow = W_bh + tid*36;          // word[p2*4 + i], j 16..31
        #pragma unroll
        for (int p2 = 0; p2 < 8; p2++)
            #pragma unroll
            for (int i = 0; i < 4; i++){
                const float* wr = w_raw + (size_t)(hb + i)*DHN + d0 + 16;
                wrow[p2*4 + i] = f2bf2(fabsf(wr[2*p2]), fabsf(wr[2*p2+1]));
            }
    }

    // epilogue thread (tid<256): b = tid>>7, hl = tid&127
    const int eb  = tid >> 7;
    const int ehl = tid & 127;
    const int ehg = (int)rank*DSL + ehl;
    const int ebg = bbase + eb;
    float a_h = 0.f, win_h = 0.f, s = 0.f;
    if (tid < 256){
        a_h   = 1.0f/taus[ehg];
        win_h = win[ehg];
        s     = r0[(size_t)ebg*DHN + ehg];
        r_own[(0*NB + eb)*144 + swz(ehl)] = sigmoidf_(s);
    }

    // ship target: packed (b0,b1) partial for h-row == tid -> rank tid>>7
    const uint32_t dj = (uint32_t)(tid >> 7);
    const uint32_t pdst0 = mapa_(smem_u32(&p_sh[(0*NRANK + (int)rank)*DSL*2 + (tid & 127)*2]), dj);
    const uint32_t PBUF = (uint32_t)(NRANK*DSL*2*4);

    __syncthreads();

    const float* np = noise + (size_t)ebg*DHN + ehg;

    for (int t = 0; t < TN; t++){
        const int buf = t & 1;

        float nv = 0.f;
        if (tid < 256) nv = np[(size_t)t*BN*DHN];

        // ---- matvec: 4h x 32d partial dots, both batches ----
        unsigned long long acc0[4] = {0,0,0,0}, acc1[4] = {0,0,0,0};
        const ulonglong2* rp0 = (const ulonglong2*)(r_own + (buf*NB + 0)*144 + dg*36);
        const ulonglong2* rp1 = (const ulonglong2*)(r_own + (buf*NB + 1)*144 + dg*36);

        // fp32-reg half (j 0..15)
        #pragma unroll
        for (int q = 0; q < 2; q++){
            ulonglong2 A = rp0[q], B = rp1[q];          // j = 4q..4q+3
            #pragma unroll
            for (int i = 0; i < 4; i++){
                fma2(acc0[i], w2[i*8 + 2*q    ], A.x);
                fma2(acc0[i], w2[i*8 + 2*q + 1], A.y);
                fma2(acc1[i], w2[i*8 + 2*q    ], B.x);
                fma2(acc1[i], w2[i*8 + 2*q + 1], B.y);
            }
        }
        #pragma unroll
        for (int q = 2; q < 4; q++){
            ulonglong2 A = rp0[q], B = rp1[q];
            #pragma unroll
            for (int i = 0; i < 4; i++){
                fma2(acc0[i], w2[i*8 + 2*q    ], A.x);
                fma2(acc0[i], w2[i*8 + 2*q + 1], A.y);
                fma2(acc1[i], w2[i*8 + 2*q    ], B.x);
                fma2(acc1[i], w2[i*8 + 2*q + 1], B.y);
            }
        }
        // bf16-smem half (j 16..31), W read once, shared by both batches
        {
            const uint4* wrow = (const uint4*)(W_bh + tid*36);
            #pragma unroll
            for (int q = 0; q < 4; q++){
                ulonglong2 A = rp0[4+q], B = rp1[4+q];  // j = 16+4q..19+4q
                uint4 wqa = wrow[2*q];                  // p2 = 2q   (i 0..3)
                uint4 wqb = wrow[2*q+1];                // p2 = 2q+1 (i 0..3)
                unsigned long long wp;
                wp = bf2f2(wqa.x); fma2(acc0[0], wp, A.x); fma2(acc1[0], wp, B.x);
                wp = bf2f2(wqa.y); fma2(acc0[1], wp, A.x); fma2(acc1[1], wp, B.x);
                wp = bf2f2(wqa.z); fma2(acc0[2], wp, A.x); fma2(acc1[2], wp, B.x);
                wp = bf2f2(wqa.w); fma2(acc0[3], wp, A.x); fma2(acc1[3], wp, B.x);
                wp = bf2f2(wqb.x); fma2(acc0[0], wp, A.y); fma2(acc1[0], wp, B.y);
                wp = bf2f2(wqb.y); fma2(acc0[1], wp, A.y); fma2(acc1[1], wp, B.y);
                wp = bf2f2(wqb.z); fma2(acc0[2], wp, A.y); fma2(acc1[2], wp, B.y);
                wp = bf2f2(wqb.w); fma2(acc0[3], wp, A.y); fma2(acc1[3], wp, B.y);
            }
        }

        // ---- reduce-scatter over dg (lane dg keeps h-row tid) ----
        float res0, res1;
        {
            float s0,s1,s2,s3, lo,hi;
            unpack2(acc0[0],lo,hi); s0 = lo+hi;
            unpack2(acc0[1],lo,hi); s1 = lo+hi;
            unpack2(acc0[2],lo,hi); s2 = lo+hi;
            unpack2(acc0[3],lo,hi); s3 = lo+hi;
            float v0 = (dg & 2) ? s0 : s2;
            float v1 = (dg & 2) ? s1 : s3;
            v0 = __shfl_xor_sync(0xffffffffu, v0, 2);
            v1 = __shfl_xor_sync(0xffffffffu, v1, 2);
            float t0 = ((dg & 2) ? s2 : s0) + v0;
            float t1 = ((dg & 2) ? s3 : s1) + v1;
            float v = (dg & 1) ? t0 : t1;
            v = __shfl_xor_sync(0xffffffffu, v, 1);
            res0 = ((dg & 1) ? t1 : t0) + v;
        }
        {
            float s0,s1,s2,s3, lo,hi;
            unpack2(acc1[0],lo,hi); s0 = lo+hi;
            unpack2(acc1[1],lo,hi); s1 = lo+hi;
            unpack2(acc1[2],lo,hi); s2 = lo+hi;
            unpack2(acc1[3],lo,hi); s3 = lo+hi;
            float v0 = (dg & 2) ? s0 : s2;
            float v1 = (dg & 2) ? s1 : s3;
            v0 = __shfl_xor_sync(0xffffffffu, v0, 2);
            v1 = __shfl_xor_sync(0xffffffffu, v1, 2);
            float t0 = ((dg & 2) ? s2 : s0) + v0;
            float t1 = ((dg & 2) ? s3 : s1) + v1;
            float v = (dg & 1) ? t0 : t1;
            v = __shfl_xor_sync(0xffffffffu, v, 1);
            res1 = ((dg & 1) ? t1 : t0) + v;
        }

        // ---- ship packed partials to the h-owning rank ----
        st_cluster_b64(pdst0 + (buf ? PBUF : 0u), pack2(res0, res1));

        cluster_arrive_();

        // flush the PREVIOUS 16-step block inside the arrive->wait gap
        if ((t & 15) == 0 && t){
            const int t0 = t - 16;
            #pragma unroll
            for (int it = 0; it < 2; it++){
                int idx = tid + it*512;
                int q  = idx & 3;
                int hl = (idx >> 2) & 127;
                int b  = idx >> 9;
                float4 vx, vs;
                vx.x = stg_x[((4*q+0)*NB + b)*DSL + hl];
                vx.y = stg_x[((4*q+1)*NB + b)*DSL + hl];
                vx.z = stg_x[((4*q+2)*NB + b)*DSL + hl];
                vx.w = stg_x[((4*q+3)*NB + b)*DSL + hl];
                vs.x = stg_s[((4*q+0)*NB + b)*DSL + hl];
                vs.y = stg_s[((4*q+1)*NB + b)*DSL + hl];
                vs.z = stg_s[((4*q+2)*NB + b)*DSL + hl];
                vs.w = stg_s[((4*q+3)*NB + b)*DSL + hl];
                size_t row = ((size_t)(bbase+b)*DHN + (int)rank*DSL + hl)*TN + t0 + 4*q;
                *(float4*)(xs    + row) = vx;
                *(float4*)(g_sig + row) = vs;
            }
        }

        cluster_wait_();

        // ---- reduce partials + epilogue for own h-slice ----
        if (tid < 256){
            const float* pb = p_sh + buf*NRANK*DSL*2 + ehl*2 + eb;
            float dot = (pb[0] + pb[DSL*2]) + (pb[2*DSL*2] + pb[3*DSL*2]);
            float xn = (1.0f - a_h)*s + a_h*dot + win_h*u_sh[eb*TN + t] + 0.1f*nv;
            stg_x[((t&15)*NB + eb)*DSL + ehl] = xn;
            s = sigmoidf_(xn);
            stg_s[((t&15)*NB + eb)*DSL + ehl] = s;
            r_own[(((t+1)&1)*NB + eb)*144 + swz(ehl)] = sigmoidf_(s);
        }
        __syncthreads();
    }

    // final block flush
    {
        const int t0 = TN - 16;
        #pragma unroll
        for (int it = 0; it < 2; it++){
            int idx = tid + it*512;
            int q  = idx & 3;
            int hl = (idx >> 2) & 127;
            int b  = idx >> 9;
            float4 vx, vs;
            vx.x = stg_x[((4*q+0)*NB + b)*DSL + hl];
            vx.y = stg_x[((4*q+1)*NB + b)*DSL + hl];
            vx.z = stg_x[((4*q+2)*NB + b)*DSL + hl];
            vx.w = stg_x[((4*q+3)*NB + b)*DSL + hl];
            vs.x = stg_s[((4*q+0)*NB + b)*DSL + hl];
            vs.y = stg_s[((4*q+1)*NB + b)*DSL + hl];
            vs.z = stg_s[((4*q+2)*NB + b)*DSL + hl];
            vs.w = stg_s[((4*q+3)*NB + b)*DSL + hl];
            size_t row = ((size_t)(bbase+b)*DHN + (int)rank*DSL + hl)*TN + t0 + 4*q;
            *(float4*)(xs    + row) = vx;
            *(float4*)(g_sig + row) = vs;
        }
    }

    cluster_arrive_();
    cluster_wait_();
}

// Partial dot products over 64-h chunks: pure DRAM streaming, zero MUFU.
__global__ void __launch_bounds__(256)
rnn_out_part(const float* __restrict__ wout)
{
    const int b  = blockIdx.x >> 3;
    const int hc = blockIdx.x & 7;
    __shared__ float wsh[64];
    if (threadIdx.x < 64) wsh[threadIdx.x] = wout[hc*64 + threadIdx.x];
    __syncthreads();

    const float4* base = (const float4*)(g_sig + ((size_t)b*DHN + hc*64)*TN);
    float a0=0.f, a1=0.f, a2=0.f, a3=0.f;
    #pragma unroll 4
    for (int h = 0; h < 64; h++){
        float wv = wsh[h];
        float4 v = base[(size_t)h*(TN/4) + threadIdx.x];
        a0 = fmaf(wv, v.x, a0);
        a1 = fmaf(wv, v.y, a1);
        a2 = fmaf(wv, v.z, a2);
        a3 = fmaf(wv, v.w, a3);
    }
    float4 o; o.x=a0; o.y=a1; o.z=a2; o.w=a3;
    ((float4*)g_part[hc][b])[threadIdx.x] = o;
}

__global__ void __launch_bounds__(256)
rnn_combine(const float* __restrict__ bias, float* __restrict__ out)
{
    const int b = blockIdx.x;
    float4 acc = {0.f,0.f,0.f,0.f};
    #pragma unroll
    for (int c = 0; c < 8; c++){
        float4 p = ((const float4*)g_part[c][b])[threadIdx.x];
        acc.x += p.x; acc.y += p.y; acc.z += p.z; acc.w += p.w;
    }
    float bz = bias[0];
    acc.x += bz; acc.y += bz; acc.z += bz; acc.w += bz;
    ((float4*)(out + (size_t)b*TN))[threadIdx.x] = acc;
}

extern "C" void kernel_launch(void* const* d_in, const int* in_sizes, int n_in,
                              void* d_out, int out_size)
{
    // metadata order: u, r0, noise, win, m, wout, _w, taus, bias
    const float* u     = (const float*)d_in[0];
    const float* r0    = (const float*)d_in[1];
    const float* noise = (const float*)d_in[2];
    const float* win   = (const float*)d_in[3];
    const float* wout  = (const float*)d_in[5];
    const float* w_raw = (const float*)d_in[6];
    const float* taus  = (const float*)d_in[7];
    const float* bias  = (const float*)d_in[8];

    float* out = (float*)d_out;                 // outputs (B, T, 1)
    float* xs  = out + (size_t)BN * TN;         // xs (B, DH, T)

    static int inited = 0;
    if (!inited){
        cudaFuncSetAttribute(rnn_main, cudaFuncAttributeMaxDynamicSharedMemorySize, SMEM_BYTES);
        inited = 1;
    }

    rnn_main<<<32*NRANK, 512, SMEM_BYTES>>>(u, r0, noise, win, w_raw, taus, xs);
    rnn_out_part<<<BN*8, 256>>>(wout);
    rnn_combine<<<BN, 256>>>(bias, out);
}